// round 1
// baseline (speedup 1.0000x reference)
#include <cuda_runtime.h>

#define NN 50000
#define NE 1000000
#define DIN 64
#define NH 8
#define D2 512

// ---------------- static device scratch (no allocation allowed) ----------------
__device__ float g_H[NN * D2];          // layer-1 pre-activation, all heads concat
__device__ float g_X2[NN * D2];         // layer-2 input (elu(elu(h')))
__device__ float g_s1[NN * NH];         // h[n] . a1  per head
__device__ float g_s2[NN * NH];         // h[n] . a2  per head
__device__ float g_h2[NN * DIN];        // layer-2 linear output
__device__ float g_t1[NN];
__device__ float g_t2[NN];
__device__ int   g_counts[NN];
__device__ int   g_cursor[NN];
__device__ int   g_offsets[NN + 1];
__device__ int   g_tgt_sorted[NE];
__device__ float g_ea_sorted[NE * NH];  // edge_attr . a3  per head, CSR order
__device__ float g_ea2_sorted[NE];      // edge_attr . a_out3, CSR order

__device__ __forceinline__ float leaky(float x) { return x >= 0.f ? x : 0.01f * x; }
__device__ __forceinline__ float elu1(float x)  { return x > 0.f ? x : expm1f(x); }

// ---------------- kernels ----------------

__global__ void k_zero() {
    int i = blockIdx.x * blockDim.x + threadIdx.x;
    if (i < NN) { g_counts[i] = 0; g_cursor[i] = 0; }
}

// H[n][h*64+j] = sum_k X[n][k] * W_heads[h][k][j]
__global__ __launch_bounds__(256) void k_gemm1(const float* __restrict__ X,
                                               const float* __restrict__ Wh) {
    __shared__ float Xs[64][65];
    __shared__ float Ws[64][65];
    int r0 = blockIdx.x * 64;
    int h  = blockIdx.y;
    int t  = threadIdx.x;
#pragma unroll
    for (int i = 0; i < 16; i++) {
        int idx = i * 256 + t;
        int r = idx >> 6, c = idx & 63;
        Xs[r][c] = (r0 + r < NN) ? X[(r0 + r) * 64 + c] : 0.f;
        Ws[r][c] = Wh[h * 4096 + idx];
    }
    __syncthreads();
    int ty = t >> 4, tx = t & 15;
    float acc[4][4] = {};
#pragma unroll 8
    for (int k = 0; k < 64; k++) {
        float a[4], b[4];
#pragma unroll
        for (int i = 0; i < 4; i++) a[i] = Xs[ty * 4 + i][k];
#pragma unroll
        for (int j = 0; j < 4; j++) b[j] = Ws[k][tx * 4 + j];
#pragma unroll
        for (int i = 0; i < 4; i++)
#pragma unroll
            for (int j = 0; j < 4; j++) acc[i][j] = fmaf(a[i], b[j], acc[i][j]);
    }
#pragma unroll
    for (int i = 0; i < 4; i++) {
        int row = r0 + ty * 4 + i;
        if (row < NN) {
#pragma unroll
            for (int j = 0; j < 4; j++)
                g_H[row * D2 + h * 64 + tx * 4 + j] = acc[i][j];
        }
    }
}

// per-node per-head attention scalars s1 = h.a1, s2 = h.a2
__global__ void k_s12(const float* __restrict__ a_heads) {
    int gw = (blockIdx.x * blockDim.x + threadIdx.x) >> 5;
    if (gw >= NN * NH) return;
    int n = gw >> 3, h = gw & 7, lane = threadIdx.x & 31;
    float hv0 = g_H[n * D2 + h * 64 + lane];
    float hv1 = g_H[n * D2 + h * 64 + lane + 32];
    const float* a = a_heads + h * 144;
    float s1 = hv0 * __ldg(a + lane)      + hv1 * __ldg(a + lane + 32);
    float s2 = hv0 * __ldg(a + 64 + lane) + hv1 * __ldg(a + 96 + lane);
#pragma unroll
    for (int o = 16; o > 0; o >>= 1) {
        s1 += __shfl_xor_sync(0xffffffffu, s1, o);
        s2 += __shfl_xor_sync(0xffffffffu, s2, o);
    }
    if (lane == 0) { g_s1[n * 8 + h] = s1; g_s2[n * 8 + h] = s2; }
}

__global__ void k_hist(const int* __restrict__ src) {
    int e = blockIdx.x * blockDim.x + threadIdx.x;
    if (e < NE) atomicAdd(&g_counts[src[e]], 1);
}

// single-block exclusive scan of counts -> offsets
__global__ void k_scan() {
    __shared__ int warp_sums[32];
    __shared__ int s_carry;
    int t = threadIdx.x;
    if (t == 0) s_carry = 0;
    __syncthreads();
    for (int base = 0; base < NN; base += 1024) {
        int v = (base + t < NN) ? g_counts[base + t] : 0;
        int x = v;
#pragma unroll
        for (int o = 1; o < 32; o <<= 1) {
            int y = __shfl_up_sync(0xffffffffu, x, o);
            if ((t & 31) >= o) x += y;
        }
        if ((t & 31) == 31) warp_sums[t >> 5] = x;
        __syncthreads();
        if (t < 32) {
            int s = warp_sums[t];
#pragma unroll
            for (int o = 1; o < 32; o <<= 1) {
                int y = __shfl_up_sync(0xffffffffu, s, o);
                if (t >= o) s += y;
            }
            warp_sums[t] = s;
        }
        __syncthreads();
        int pre = (t >= 32) ? warp_sums[(t >> 5) - 1] : 0;
        int incl = x + pre;
        int excl = incl - v;
        if (base + t < NN) g_offsets[base + t] = s_carry + excl;
        __syncthreads();
        if (t == 1023) s_carry += incl;
        __syncthreads();
    }
    if (t == 0) g_offsets[NN] = s_carry;
}

// scatter edges into CSR order; precompute edge_attr dot products
__global__ void k_scatter(const int* __restrict__ src, const int* __restrict__ tgt,
                          const float* __restrict__ ea,
                          const float* __restrict__ a_heads,
                          const float* __restrict__ a_out) {
    __shared__ float sA[NH * 16];
    __shared__ float sA2[16];
    int t = threadIdx.x;
    if (t < NH * 16) sA[t] = a_heads[(t >> 4) * 144 + 128 + (t & 15)];
    if (t < 16) sA2[t] = a_out[128 + t];
    __syncthreads();
    int e = blockIdx.x * blockDim.x + t;
    if (e >= NE) return;
    int s = src[e];
    int p = atomicAdd(&g_cursor[s], 1);
    int idx = g_offsets[s] + p;
    g_tgt_sorted[idx] = tgt[e];
    float eav[16];
    const float4* ep = (const float4*)(ea + e * 16);
#pragma unroll
    for (int q = 0; q < 4; q++) {
        float4 v = ep[q];
        eav[q * 4 + 0] = v.x; eav[q * 4 + 1] = v.y;
        eav[q * 4 + 2] = v.z; eav[q * 4 + 3] = v.w;
    }
    float d2 = 0.f;
#pragma unroll
    for (int k = 0; k < 16; k++) d2 = fmaf(eav[k], sA2[k], d2);
    g_ea2_sorted[idx] = d2;
#pragma unroll
    for (int h = 0; h < NH; h++) {
        float d = 0.f;
#pragma unroll
        for (int k = 0; k < 16; k++) d = fmaf(eav[k], sA[h * 16 + k], d);
        g_ea_sorted[idx * 8 + h] = d;
    }
}

// layer-1 fused attention + aggregation: one warp per node, all 8 heads
__global__ __launch_bounds__(256) void k_agg1() {
    int w = (blockIdx.x * blockDim.x + threadIdx.x) >> 5;
    if (w >= NN) return;
    int lane = threadIdx.x & 31;
    int beg = g_offsets[w], end = g_offsets[w + 1];
    float s1v = (lane < 8) ? g_s1[w * 8 + lane] : 0.f;
    float4 a0 = make_float4(0, 0, 0, 0), a1 = a0, a2 = a0, a3 = a0;
    float denom = 0.f;
    int myhead = lane >> 2;
    for (int i = beg; i < end; i++) {
        int tg = g_tgt_sorted[i];
        float wgt = 0.f;
        if (lane < 8) {
            float sc = s1v + g_s2[tg * 8 + lane] + g_ea_sorted[i * 8 + lane];
            sc = leaky(sc);
            wgt = __expf(sc);
            denom += wgt;
        }
        float wl = __shfl_sync(0xffffffffu, wgt, myhead);
        const float4* hp = (const float4*)(g_H + tg * D2 + lane * 16);
        float4 h0 = hp[0], h1 = hp[1], h2v = hp[2], h3 = hp[3];
        a0.x = fmaf(wl, h0.x, a0.x); a0.y = fmaf(wl, h0.y, a0.y);
        a0.z = fmaf(wl, h0.z, a0.z); a0.w = fmaf(wl, h0.w, a0.w);
        a1.x = fmaf(wl, h1.x, a1.x); a1.y = fmaf(wl, h1.y, a1.y);
        a1.z = fmaf(wl, h1.z, a1.z); a1.w = fmaf(wl, h1.w, a1.w);
        a2.x = fmaf(wl, h2v.x, a2.x); a2.y = fmaf(wl, h2v.y, a2.y);
        a2.z = fmaf(wl, h2v.z, a2.z); a2.w = fmaf(wl, h2v.w, a2.w);
        a3.x = fmaf(wl, h3.x, a3.x); a3.y = fmaf(wl, h3.y, a3.y);
        a3.z = fmaf(wl, h3.z, a3.z); a3.w = fmaf(wl, h3.w, a3.w);
    }
    float d = __shfl_sync(0xffffffffu, denom, myhead);
    float inv = 1.f / (d + 1e-16f);
    float4* op = (float4*)(g_X2 + w * D2 + lane * 16);
    float4 o;
    o.x = elu1(elu1(a0.x * inv)); o.y = elu1(elu1(a0.y * inv));
    o.z = elu1(elu1(a0.z * inv)); o.w = elu1(elu1(a0.w * inv));
    op[0] = o;
    o.x = elu1(elu1(a1.x * inv)); o.y = elu1(elu1(a1.y * inv));
    o.z = elu1(elu1(a1.z * inv)); o.w = elu1(elu1(a1.w * inv));
    op[1] = o;
    o.x = elu1(elu1(a2.x * inv)); o.y = elu1(elu1(a2.y * inv));
    o.z = elu1(elu1(a2.z * inv)); o.w = elu1(elu1(a2.w * inv));
    op[2] = o;
    o.x = elu1(elu1(a3.x * inv)); o.y = elu1(elu1(a3.y * inv));
    o.z = elu1(elu1(a3.z * inv)); o.w = elu1(elu1(a3.w * inv));
    op[3] = o;
}

// h2 = X2 @ W_out   (50000 x 512 @ 512 x 64)
__global__ __launch_bounds__(256) void k_gemm2(const float* __restrict__ Wo) {
    __shared__ float Xs[64][65];
    __shared__ float Ws[64][65];
    int r0 = blockIdx.x * 64;
    int t = threadIdx.x;
    int ty = t >> 4, tx = t & 15;
    float acc[4][4] = {};
    for (int kk = 0; kk < 8; kk++) {
        __syncthreads();
#pragma unroll
        for (int i = 0; i < 16; i++) {
            int idx = i * 256 + t;
            int r = idx >> 6, c = idx & 63;
            Xs[r][c] = (r0 + r < NN) ? g_X2[(r0 + r) * D2 + kk * 64 + c] : 0.f;
            Ws[r][c] = Wo[(kk * 64 + r) * 64 + c];
        }
        __syncthreads();
#pragma unroll 8
        for (int k = 0; k < 64; k++) {
            float a[4], b[4];
#pragma unroll
            for (int i = 0; i < 4; i++) a[i] = Xs[ty * 4 + i][k];
#pragma unroll
            for (int j = 0; j < 4; j++) b[j] = Ws[k][tx * 4 + j];
#pragma unroll
            for (int i = 0; i < 4; i++)
#pragma unroll
                for (int j = 0; j < 4; j++) acc[i][j] = fmaf(a[i], b[j], acc[i][j]);
        }
    }
#pragma unroll
    for (int i = 0; i < 4; i++) {
        int row = r0 + ty * 4 + i;
        if (row < NN) {
#pragma unroll
            for (int j = 0; j < 4; j++)
                g_h2[row * 64 + tx * 4 + j] = acc[i][j];
        }
    }
}

__global__ void k_t12(const float* __restrict__ a_out) {
    int n = (blockIdx.x * blockDim.x + threadIdx.x) >> 5;
    if (n >= NN) return;
    int lane = threadIdx.x & 31;
    float v0 = g_h2[n * 64 + lane], v1 = g_h2[n * 64 + lane + 32];
    float t1 = v0 * __ldg(a_out + lane)      + v1 * __ldg(a_out + lane + 32);
    float t2 = v0 * __ldg(a_out + 64 + lane) + v1 * __ldg(a_out + 96 + lane);
#pragma unroll
    for (int o = 16; o > 0; o >>= 1) {
        t1 += __shfl_xor_sync(0xffffffffu, t1, o);
        t2 += __shfl_xor_sync(0xffffffffu, t2, o);
    }
    if (lane == 0) { g_t1[n] = t1; g_t2[n] = t2; }
}

// layer-2 aggregation + elu + log_softmax, one warp per node
__global__ __launch_bounds__(256) void k_agg2(float* __restrict__ out) {
    int n = (blockIdx.x * blockDim.x + threadIdx.x) >> 5;
    if (n >= NN) return;
    int lane = threadIdx.x & 31;
    int beg = g_offsets[n], end = g_offsets[n + 1];
    float t1v = g_t1[n];
    float acc0 = 0.f, acc1 = 0.f, denom = 0.f;
    for (int i = beg; i < end; i++) {
        int tg = g_tgt_sorted[i];
        float sc = leaky(t1v + g_t2[tg] + g_ea2_sorted[i]);
        float wgt = __expf(sc);
        denom += wgt;
        acc0 = fmaf(wgt, g_h2[tg * 64 + lane], acc0);
        acc1 = fmaf(wgt, g_h2[tg * 64 + lane + 32], acc1);
    }
    float inv = 1.f / (denom + 1e-16f);
    float y0 = elu1(acc0 * inv);
    float y1 = elu1(acc1 * inv);
    float m = fmaxf(y0, y1);
#pragma unroll
    for (int o = 16; o > 0; o >>= 1) m = fmaxf(m, __shfl_xor_sync(0xffffffffu, m, o));
    float se = __expf(y0 - m) + __expf(y1 - m);
#pragma unroll
    for (int o = 16; o > 0; o >>= 1) se += __shfl_xor_sync(0xffffffffu, se, o);
    float ls = m + logf(se);
    out[n * 64 + lane] = y0 - ls;
    out[n * 64 + lane + 32] = y1 - ls;
}

// ---------------- launcher ----------------
extern "C" void kernel_launch(void* const* d_in, const int* in_sizes, int n_in,
                              void* d_out, int out_size) {
    const float* X        = (const float*)d_in[0];
    const float* ea       = (const float*)d_in[1];
    const float* W_heads  = (const float*)d_in[2];
    const float* a_heads  = (const float*)d_in[3];
    const float* W_out    = (const float*)d_in[4];
    const float* a_out    = (const float*)d_in[5];
    const int*   eidx     = (const int*)d_in[6];
    const int* src = eidx;
    const int* tgt = eidx + NE;
    float* out = (float*)d_out;

    k_zero<<<(NN + 255) / 256, 256>>>();
    k_gemm1<<<dim3((NN + 63) / 64, NH), 256>>>(X, W_heads);
    k_s12<<<(NN * NH * 32) / 256, 256>>>(a_heads);
    k_hist<<<(NE + 255) / 256, 256>>>(src);
    k_scan<<<1, 1024>>>();
    k_scatter<<<(NE + 255) / 256, 256>>>(src, tgt, ea, a_heads, a_out);
    k_agg1<<<(NN * 32) / 256, 256>>>();
    k_gemm2<<<(NN + 63) / 64, 256>>>(W_out);
    k_t12<<<(NN * 32 + 255) / 256, 256>>>(a_out);
    k_agg2<<<(NN * 32 + 255) / 256, 256>>>(out);
}

// round 2
// speedup vs baseline: 1.2400x; 1.2400x over previous
#include <cuda_runtime.h>

#define NN 50000
#define NE 1000000
#define DIN 64
#define NH 8
#define D2 512

// ---------------- static device scratch ----------------
__device__ float g_H[NN * D2];          // layer-1: per-head aggregated X (alpha-weighted), later reused
__device__ float g_X2[NN * D2];         // layer-2 input
__device__ float g_s1[NN * NH];
__device__ float g_s2[NN * NH];
__device__ float g_h2[NN * DIN];
__device__ float g_t1[NN];
__device__ float g_t2[NN];
__device__ float g_w12[2][NH][64];      // W_h @ a1, W_h @ a2
__device__ int   g_counts[NN];
__device__ int   g_cursor[NN];
__device__ int   g_offsets[NN + 1];
__device__ int   g_tgt_sorted[NE];
__device__ float g_ea_sorted[NE * NH];
__device__ float g_ea2_sorted[NE];

__device__ __forceinline__ float leaky(float x) { return x >= 0.f ? x : 0.01f * x; }
__device__ __forceinline__ float elu1(float x)  { return x > 0.f ? x : expm1f(x); }

// ---------------- kernels ----------------

__global__ void k_zero() {
    int i = blockIdx.x * blockDim.x + threadIdx.x;
    if (i < NN) { g_counts[i] = 0; g_cursor[i] = 0; }
}

// w12[which][h][k] = sum_j W_heads[h][k][j] * a_heads[h][which*64 + j]
__global__ void k_w12(const float* __restrict__ Wh, const float* __restrict__ ah) {
    int tid = threadIdx.x;                 // 1024 threads, 1 block
    int which = tid >> 9;
    int h = (tid >> 6) & 7;
    int k = tid & 63;
    const float* wrow = Wh + h * 4096 + k * 64;
    const float* a = ah + h * 144 + which * 64;
    float s = 0.f;
#pragma unroll 16
    for (int j = 0; j < 64; j++) s = fmaf(wrow[j], a[j], s);
    g_w12[which][h][k] = s;
}

// s1[n,h] = X[n] . w12[0][h],  s2[n,h] = X[n] . w12[1][h]
__global__ void k_s12(const float* __restrict__ X) {
    int n = (blockIdx.x * blockDim.x + threadIdx.x) >> 5;
    if (n >= NN) return;
    int lane = threadIdx.x & 31;
    float x0 = X[n * 64 + lane], x1 = X[n * 64 + lane + 32];
#pragma unroll
    for (int c = 0; c < 16; c++) {
        int which = c >> 3, h = c & 7;
        float p = x0 * g_w12[which][h][lane] + x1 * g_w12[which][h][lane + 32];
#pragma unroll
        for (int o = 16; o > 0; o >>= 1) p += __shfl_xor_sync(0xffffffffu, p, o);
        if (lane == 0) {
            if (which == 0) g_s1[n * 8 + h] = p; else g_s2[n * 8 + h] = p;
        }
    }
}

__global__ void k_hist(const int* __restrict__ src) {
    int e = blockIdx.x * blockDim.x + threadIdx.x;
    if (e < NE) atomicAdd(&g_counts[src[e]], 1);
}

__global__ void k_scan() {
    __shared__ int warp_sums[32];
    __shared__ int s_carry;
    int t = threadIdx.x;
    if (t == 0) s_carry = 0;
    __syncthreads();
    for (int base = 0; base < NN; base += 1024) {
        int v = (base + t < NN) ? g_counts[base + t] : 0;
        int x = v;
#pragma unroll
        for (int o = 1; o < 32; o <<= 1) {
            int y = __shfl_up_sync(0xffffffffu, x, o);
            if ((t & 31) >= o) x += y;
        }
        if ((t & 31) == 31) warp_sums[t >> 5] = x;
        __syncthreads();
        if (t < 32) {
            int s = warp_sums[t];
#pragma unroll
            for (int o = 1; o < 32; o <<= 1) {
                int y = __shfl_up_sync(0xffffffffu, s, o);
                if (t >= o) s += y;
            }
            warp_sums[t] = s;
        }
        __syncthreads();
        int pre = (t >= 32) ? warp_sums[(t >> 5) - 1] : 0;
        int incl = x + pre;
        int excl = incl - v;
        if (base + t < NN) g_offsets[base + t] = s_carry + excl;
        __syncthreads();
        if (t == 1023) s_carry += incl;
        __syncthreads();
    }
    if (t == 0) g_offsets[NN] = s_carry;
}

__global__ void k_scatter(const int* __restrict__ src, const int* __restrict__ tgt,
                          const float* __restrict__ ea,
                          const float* __restrict__ a_heads,
                          const float* __restrict__ a_out) {
    __shared__ float sA[NH * 16];
    __shared__ float sA2[16];
    int t = threadIdx.x;
    if (t < NH * 16) sA[t] = a_heads[(t >> 4) * 144 + 128 + (t & 15)];
    if (t < 16) sA2[t] = a_out[128 + t];
    __syncthreads();
    int e = blockIdx.x * blockDim.x + t;
    if (e >= NE) return;
    int s = src[e];
    int p = atomicAdd(&g_cursor[s], 1);
    int idx = g_offsets[s] + p;
    g_tgt_sorted[idx] = tgt[e];
    float eav[16];
    const float4* ep = (const float4*)(ea + e * 16);
#pragma unroll
    for (int q = 0; q < 4; q++) {
        float4 v = ep[q];
        eav[q * 4 + 0] = v.x; eav[q * 4 + 1] = v.y;
        eav[q * 4 + 2] = v.z; eav[q * 4 + 3] = v.w;
    }
    float d2 = 0.f;
#pragma unroll
    for (int k = 0; k < 16; k++) d2 = fmaf(eav[k], sA2[k], d2);
    g_ea2_sorted[idx] = d2;
#pragma unroll
    for (int h = 0; h < NH; h++) {
        float d = 0.f;
#pragma unroll
        for (int k = 0; k < 16; k++) d = fmaf(eav[k], sA[h * 16 + k], d);
        g_ea_sorted[idx * 8 + h] = d;
    }
}

// layer-1 aggregation over X (pre-projection): one warp per node.
// g_H[n][h*64 + c] = (1/denom_h) * sum_e exp(leaky(score)) * X[tgt_e][c]
__global__ __launch_bounds__(256) void k_agg1(const float* __restrict__ X) {
    int w = (blockIdx.x * blockDim.x + threadIdx.x) >> 5;
    if (w >= NN) return;
    int lane = threadIdx.x & 31;
    int beg = g_offsets[w], end = g_offsets[w + 1];
    float s1v = (lane < 8) ? g_s1[w * 8 + lane] : 0.f;
    float acc[8][2] = {};
    float denom = 0.f;
    for (int i = beg; i < end; i++) {
        int tg = g_tgt_sorted[i];
        float wgt = 0.f;
        if (lane < 8) {
            float sc = s1v + g_s2[tg * 8 + lane] + g_ea_sorted[i * 8 + lane];
            wgt = __expf(leaky(sc));
            denom += wgt;
        }
        float2 xv = ((const float2*)(X + tg * 64))[lane];
#pragma unroll
        for (int h = 0; h < 8; h++) {
            float wl = __shfl_sync(0xffffffffu, wgt, h);
            acc[h][0] = fmaf(wl, xv.x, acc[h][0]);
            acc[h][1] = fmaf(wl, xv.y, acc[h][1]);
        }
    }
#pragma unroll
    for (int h = 0; h < 8; h++) {
        float d = __shfl_sync(0xffffffffu, denom, h);
        float inv = 1.f / (d + 1e-16f);
        ((float2*)(g_H + w * D2 + h * 64))[lane] =
            make_float2(acc[h][0] * inv, acc[h][1] * inv);
    }
}

// X2[n][h*64+j] = elu(elu( sum_k aggX[n][h][k] * W_heads[h][k][j] ))
__global__ __launch_bounds__(256) void k_gemm1b(const float* __restrict__ Wh) {
    __shared__ float Xs[64][65];
    __shared__ float Ws[64][65];
    int r0 = blockIdx.x * 64;
    int h  = blockIdx.y;
    int t  = threadIdx.x;
#pragma unroll
    for (int i = 0; i < 16; i++) {
        int idx = i * 256 + t;
        int r = idx >> 6, c = idx & 63;
        Xs[r][c] = (r0 + r < NN) ? g_H[(r0 + r) * D2 + h * 64 + c] : 0.f;
        Ws[r][c] = Wh[h * 4096 + idx];
    }
    __syncthreads();
    int ty = t >> 4, tx = t & 15;
    float acc[4][4] = {};
#pragma unroll 8
    for (int k = 0; k < 64; k++) {
        float a[4], b[4];
#pragma unroll
        for (int i = 0; i < 4; i++) a[i] = Xs[ty * 4 + i][k];
#pragma unroll
        for (int j = 0; j < 4; j++) b[j] = Ws[k][tx * 4 + j];
#pragma unroll
        for (int i = 0; i < 4; i++)
#pragma unroll
            for (int j = 0; j < 4; j++) acc[i][j] = fmaf(a[i], b[j], acc[i][j]);
    }
#pragma unroll
    for (int i = 0; i < 4; i++) {
        int row = r0 + ty * 4 + i;
        if (row < NN) {
#pragma unroll
            for (int j = 0; j < 4; j++)
                g_X2[row * D2 + h * 64 + tx * 4 + j] = elu1(elu1(acc[i][j]));
        }
    }
}

// h2 = X2 @ W_out
__global__ __launch_bounds__(256) void k_gemm2(const float* __restrict__ Wo) {
    __shared__ float Xs[64][65];
    __shared__ float Ws[64][65];
    int r0 = blockIdx.x * 64;
    int t = threadIdx.x;
    int ty = t >> 4, tx = t & 15;
    float acc[4][4] = {};
    for (int kk = 0; kk < 8; kk++) {
        __syncthreads();
#pragma unroll
        for (int i = 0; i < 16; i++) {
            int idx = i * 256 + t;
            int r = idx >> 6, c = idx & 63;
            Xs[r][c] = (r0 + r < NN) ? g_X2[(r0 + r) * D2 + kk * 64 + c] : 0.f;
            Ws[r][c] = Wo[(kk * 64 + r) * 64 + c];
        }
        __syncthreads();
#pragma unroll 8
        for (int k = 0; k < 64; k++) {
            float a[4], b[4];
#pragma unroll
            for (int i = 0; i < 4; i++) a[i] = Xs[ty * 4 + i][k];
#pragma unroll
            for (int j = 0; j < 4; j++) b[j] = Ws[k][tx * 4 + j];
#pragma unroll
            for (int i = 0; i < 4; i++)
#pragma unroll
                for (int j = 0; j < 4; j++) acc[i][j] = fmaf(a[i], b[j], acc[i][j]);
        }
    }
#pragma unroll
    for (int i = 0; i < 4; i++) {
        int row = r0 + ty * 4 + i;
        if (row < NN) {
#pragma unroll
            for (int j = 0; j < 4; j++)
                g_h2[row * 64 + tx * 4 + j] = acc[i][j];
        }
    }
}

__global__ void k_t12(const float* __restrict__ a_out) {
    int n = (blockIdx.x * blockDim.x + threadIdx.x) >> 5;
    if (n >= NN) return;
    int lane = threadIdx.x & 31;
    float v0 = g_h2[n * 64 + lane], v1 = g_h2[n * 64 + lane + 32];
    float t1 = v0 * __ldg(a_out + lane)      + v1 * __ldg(a_out + lane + 32);
    float t2 = v0 * __ldg(a_out + 64 + lane) + v1 * __ldg(a_out + 96 + lane);
#pragma unroll
    for (int o = 16; o > 0; o >>= 1) {
        t1 += __shfl_xor_sync(0xffffffffu, t1, o);
        t2 += __shfl_xor_sync(0xffffffffu, t2, o);
    }
    if (lane == 0) { g_t1[n] = t1; g_t2[n] = t2; }
}

__global__ __launch_bounds__(256) void k_agg2(float* __restrict__ out) {
    int n = (blockIdx.x * blockDim.x + threadIdx.x) >> 5;
    if (n >= NN) return;
    int lane = threadIdx.x & 31;
    int beg = g_offsets[n], end = g_offsets[n + 1];
    float t1v = g_t1[n];
    float acc0 = 0.f, acc1 = 0.f, denom = 0.f;
    for (int i = beg; i < end; i++) {
        int tg = g_tgt_sorted[i];
        float sc = leaky(t1v + g_t2[tg] + g_ea2_sorted[i]);
        float wgt = __expf(sc);
        denom += wgt;
        acc0 = fmaf(wgt, g_h2[tg * 64 + lane], acc0);
        acc1 = fmaf(wgt, g_h2[tg * 64 + lane + 32], acc1);
    }
    float inv = 1.f / (denom + 1e-16f);
    float y0 = elu1(acc0 * inv);
    float y1 = elu1(acc1 * inv);
    float m = fmaxf(y0, y1);
#pragma unroll
    for (int o = 16; o > 0; o >>= 1) m = fmaxf(m, __shfl_xor_sync(0xffffffffu, m, o));
    float se = __expf(y0 - m) + __expf(y1 - m);
#pragma unroll
    for (int o = 16; o > 0; o >>= 1) se += __shfl_xor_sync(0xffffffffu, se, o);
    float ls = m + logf(se);
    out[n * 64 + lane] = y0 - ls;
    out[n * 64 + lane + 32] = y1 - ls;
}

// ---------------- launcher ----------------
extern "C" void kernel_launch(void* const* d_in, const int* in_sizes, int n_in,
                              void* d_out, int out_size) {
    const float* X        = (const float*)d_in[0];
    const float* ea       = (const float*)d_in[1];
    const float* W_heads  = (const float*)d_in[2];
    const float* a_heads  = (const float*)d_in[3];
    const float* W_out    = (const float*)d_in[4];
    const float* a_out    = (const float*)d_in[5];
    const int*   eidx     = (const int*)d_in[6];
    const int* src = eidx;
    const int* tgt = eidx + NE;
    float* out = (float*)d_out;

    k_zero<<<(NN + 255) / 256, 256>>>();
    k_w12<<<1, 1024>>>(W_heads, a_heads);
    k_s12<<<(NN * 32 + 255) / 256, 256>>>(X);
    k_hist<<<(NE + 255) / 256, 256>>>(src);
    k_scan<<<1, 1024>>>();
    k_scatter<<<(NE + 255) / 256, 256>>>(src, tgt, ea, a_heads, a_out);
    k_agg1<<<(NN * 32 + 255) / 256, 256>>>(X);
    k_gemm1b<<<dim3((NN + 63) / 64, NH), 256>>>(W_heads);
    k_gemm2<<<(NN + 63) / 64, 256>>>(W_out);
    k_t12<<<(NN * 32 + 255) / 256, 256>>>(a_out);
    k_agg2<<<(NN * 32 + 255) / 256, 256>>>(out);
}